// round 16
// baseline (speedup 1.0000x reference)
#include <cuda_runtime.h>
#include <cuda_fp16.h>
#include <cstdint>
#include <cstddef>

// BahdanauAttention B=16, T=8192, D=256, U=256 fp32.
// Baseline-PTX (ptxas sm_100): fp16 mma.sync + ldmatrix, SINGLE persistent kernel.
// TM=128 tiles with 32x64 warp tiles: 25% less LDSM traffic per row (L1TEX was
// the measured 53.9% bottleneck). Single A buffer; next-tile LDGs issued into the
// registers freed by the epilogue (acc/pf sharing), STS after last A-read barrier.

#define Bn 16
#define Tn 8192
#define Dn 256
#define Un 256
#define TM 128                      // score tile M
#define TPB 64                      // tiles per batch
#define NTILES (Bn * TPB)           // 1024
#define GRID_SCORE 148
#define NPROD 128                   // producer CTAs (8 per batch)

__device__ float g_escore[Bn * Tn];        // exp(score)
__device__ float g_biasq[Bn * Un];
__device__ float g_zp[NTILES * 4];         // per-tile partial sums of exp (4 warps)
__device__ float g_partial[NTILES * Dn];   // per-tile unnormalized context partials
__device__ int   g_done;                   // biasq producer flag
__device__ int   g_tiles;                  // CTA tile-loop completion counter
__device__ int   g_fin;                    // finalize completion counter

// ---------------- helpers ----------------

__device__ __forceinline__ __half2 htanh2(__half2 x) {
    uint32_t xi = *(uint32_t*)&x, yo;
    asm("tanh.approx.f16x2 %0, %1;" : "=r"(yo) : "r"(xi));
    return *(__half2*)&yo;
}

__device__ __forceinline__ uint32_t pack_half2(float x, float y) {
    __half2 h = __floats2half2_rn(x, y);
    return *(uint32_t*)&h;
}

__device__ __forceinline__ uint32_t smem_u32(const void* p) {
    uint32_t a;
    asm("{ .reg .u64 t; cvta.to.shared.u64 t, %1; cvt.u32.u64 %0, t; }" : "=r"(a) : "l"(p));
    return a;
}

__device__ __forceinline__ void mma_fp16(float* c, const uint32_t* a, uint32_t b0, uint32_t b1) {
    asm volatile(
        "mma.sync.aligned.m16n8k16.row.col.f32.f16.f16.f32 "
        "{%0,%1,%2,%3},{%4,%5,%6,%7},{%8,%9},{%0,%1,%2,%3};"
        : "+f"(c[0]), "+f"(c[1]), "+f"(c[2]), "+f"(c[3])
        : "r"(a[0]), "r"(a[1]), "r"(a[2]), "r"(a[3]), "r"(b0), "r"(b1));
}

#define LDSM4(r, addr) \
    asm volatile("ldmatrix.sync.aligned.m8n8.x4.shared.b16 {%0,%1,%2,%3}, [%4];" \
                 : "=r"((r)[0]), "=r"((r)[1]), "=r"((r)[2]), "=r"((r)[3]) : "r"(addr))

// ---------------- smem layout (bytes) ----------------
#define SAW 132
#define SM_A 0                              // 128 rows x 132 words x 4B = 67584
#define SM_B 67584                          // 256 u-rows x 132 words x 4B = 135168
#define SM_SROW 202752                      // 128 x 4 floats = 2048
#define SM_SES 204800                       // 128 floats = 512
#define SM_SPART 205312                     // 4 x 128 float2 = 4096
#define SM_TOTAL 209408

// ---------------- the single persistent kernel ----------------
// 512 threads (16 warps). Warp (mwarp=wid&3 -> 32 rows, nwarp=wid>>2 -> 64 cols).

__global__ __launch_bounds__(512, 1)
void score_kernel(const float* __restrict__ values, const float* __restrict__ W1,
                  const float* __restrict__ Vw, const float* __restrict__ query,
                  const float* __restrict__ W2, const float* __restrict__ W2b,
                  const float* __restrict__ W1b,
                  float* __restrict__ ctx_out, float* __restrict__ w_out) {
    extern __shared__ char smem[];
    uint32_t* sA = (uint32_t*)smem;
    uint32_t* sB = (uint32_t*)(smem + SM_B);
    float* srow = (float*)(smem + SM_SROW);
    float* ses = (float*)(smem + SM_SES);
    float2* spart = (float2*)(smem + SM_SPART);

    const int tid = threadIdx.x;
    const int wid = tid >> 5, lane = tid & 31;
    const int mwarp = wid & 3, nwarp = wid >> 2;
    const int g = lane >> 2, tig = lane & 3;

    // Stage B once: W1[k][u] -> sB[u][kp] (half2 of k-pair).
#pragma unroll 4
    for (int i = tid; i < 256 * 128; i += 512) {
        int u = i & 255, kp = i >> 8;
        float x0 = __ldg(W1 + (size_t)(2 * kp) * Un + u);
        float x1 = __ldg(W1 + (size_t)(2 * kp + 1) * Un + u);
        sB[u * SAW + kp] = pack_half2(x0, x1);
    }

    const uint32_t sbA = smem_u32(sA), sbB = smem_u32(sB);
    const int t4 = lane >> 3, row_in = lane & 7;
    uint32_t adA[2];
#pragma unroll
    for (int mt = 0; mt < 2; ++mt) {
        int r = mwarp * 32 + mt * 16 + ((t4 & 1) << 3) + row_in;
        adA[mt] = sbA + (uint32_t)((r * SAW + ((t4 >> 1) << 2)) << 2);
    }
    uint32_t adB[4];
#pragma unroll
    for (int np = 0; np < 4; ++np) {
        int u = nwarp * 64 + np * 16 + ((t4 >> 1) << 3) + row_in;
        adB[np] = sbB + (uint32_t)((u * SAW + ((t4 & 1) << 2)) << 2);
    }

    // Prologue: stage first tile (128 rows x 256 cols) into A buffer.
    {
        const int tile = blockIdx.x;
        const float4* v4 = (const float4*)(values + ((size_t)(tile >> 6) * Tn + (tile & 63) * TM) * Dn);
        uint2* dst = (uint2*)sA;
#pragma unroll
        for (int j = 0; j < 16; ++j) {
            int i = tid + j * 512;
            float4 x = __ldg(v4 + i);
            dst[(i >> 6) * 66 + (i & 63)] = make_uint2(pack_half2(x.x, x.y), pack_half2(x.z, x.w));
        }
    }
    __syncthreads();

    // Producer pre-phase: CTA k (k < 128) computes biasq[b, u0:u0+32).
    if (blockIdx.x < NPROD) {
        const int b = blockIdx.x >> 3;
        const int u0 = (blockIdx.x & 7) * 32;
        float* qsh = (float*)spart;               // 256 floats
        float* psh = srow;                        // 16 x 32 floats
        if (tid < Dn) qsh[tid] = __ldg(query + b * Dn + tid);
        __syncthreads();
        const int ul = tid & 31, dp = tid >> 5;
        const float* W2c = W2 + (size_t)(dp * 16) * Un + u0 + ul;
        const float* qc = qsh + dp * 16;
        float a0 = 0.f, a1 = 0.f, a2 = 0.f, a3 = 0.f;
#pragma unroll
        for (int d = 0; d < 16; d += 4) {
            a0 += qc[d] * __ldg(W2c + (size_t)d * Un);
            a1 += qc[d + 1] * __ldg(W2c + (size_t)(d + 1) * Un);
            a2 += qc[d + 2] * __ldg(W2c + (size_t)(d + 2) * Un);
            a3 += qc[d + 3] * __ldg(W2c + (size_t)(d + 3) * Un);
        }
        psh[dp * 32 + ul] = (a0 + a1) + (a2 + a3);
        __syncthreads();
        if (tid < 32) {
            float s = 0.f;
#pragma unroll
            for (int p = 0; p < 16; ++p) s += psh[p * 32 + tid];
            int uu = u0 + tid;
            g_biasq[b * Un + uu] = s + __ldg(W2b + uu) + __ldg(W1b + uu);
        }
        __threadfence();
        __syncthreads();
        if (tid == 0) atomicAdd(&g_done, 1);
    }
    __syncthreads();   // spart/srow scratch free again

    const int c2 = tid & 127, grp = tid >> 7;
    const int ncta = (NTILES - blockIdx.x + GRID_SCORE - 1) / GRID_SCORE;

    for (int it = 0; it < ncta; ++it) {
        const int tile = blockIdx.x + it * GRID_SCORE;
        const int b = tile >> 6;
        const int t0 = (tile & 63) * TM;
        const int ntile = tile + GRID_SCORE;
        const int has_next = ntile < NTILES;
        const float4* v4n = has_next
            ? (const float4*)(values + ((size_t)(ntile >> 6) * Tn + (ntile & 63) * TM) * Dn)
            : (const float4*)values;

        // ---- MMA over K=256, tile 128x256 ----
        float acc[2][8][4];
#pragma unroll
        for (int mt = 0; mt < 2; ++mt)
#pragma unroll
            for (int nt = 0; nt < 8; ++nt)
#pragma unroll
                for (int q = 0; q < 4; ++q) acc[mt][nt][q] = 0.f;

#pragma unroll
        for (int ks = 0; ks < 16; ++ks) {
            const uint32_t ko = (uint32_t)ks * 32;
            uint32_t a0[4], a1[4], b0[4], b1[4], b2[4], b3[4];
            LDSM4(a0, adA[0] + ko);
            LDSM4(a1, adA[1] + ko);
            LDSM4(b0, adB[0] + ko);
            LDSM4(b1, adB[1] + ko);
            LDSM4(b2, adB[2] + ko);
            LDSM4(b3, adB[3] + ko);
            mma_fp16(acc[0][0], a0, b0[0], b0[1]);
            mma_fp16(acc[1][0], a1, b0[0], b0[1]);
            mma_fp16(acc[0][1], a0, b0[2], b0[3]);
            mma_fp16(acc[1][1], a1, b0[2], b0[3]);
            mma_fp16(acc[0][2], a0, b1[0], b1[1]);
            mma_fp16(acc[1][2], a1, b1[0], b1[1]);
            mma_fp16(acc[0][3], a0, b1[2], b1[3]);
            mma_fp16(acc[1][3], a1, b1[2], b1[3]);
            mma_fp16(acc[0][4], a0, b2[0], b2[1]);
            mma_fp16(acc[1][4], a1, b2[0], b2[1]);
            mma_fp16(acc[0][5], a0, b2[2], b2[3]);
            mma_fp16(acc[1][5], a1, b2[2], b2[3]);
            mma_fp16(acc[0][6], a0, b3[0], b3[1]);
            mma_fp16(acc[1][6], a1, b3[0], b3[1]);
            mma_fp16(acc[0][7], a0, b3[2], b3[3]);
            mma_fp16(acc[1][7], a1, b3[2], b3[3]);
        }

        // Gate first epilogue on biasq producers.
        if (it == 0) {
            if (tid == 0) {
                while (atomicAdd(&g_done, 0) < NPROD) __nanosleep(64);
            }
            __syncthreads();
            __threadfence();
        }

        // ---- Epilogue: tanh(acc + biasq) * Vw -> srow (consumes acc) ----
        {
            const float* bq = g_biasq + b * Un;
            float rowsum[2][2] = {{0.f, 0.f}, {0.f, 0.f}};
#pragma unroll
            for (int nt = 0; nt < 8; ++nt) {
                int c = nwarp * 64 + nt * 8 + 2 * tig;
                float2 bq2 = __ldg((const float2*)(bq + c));
                float2 vv = __ldg((const float2*)(Vw + c));
#pragma unroll
                for (int mt = 0; mt < 2; ++mt) {
                    __half2 x01 = __floats2half2_rn(acc[mt][nt][0] + bq2.x, acc[mt][nt][1] + bq2.y);
                    float2 f01 = __half22float2(htanh2(x01));
                    rowsum[mt][0] += f01.x * vv.x + f01.y * vv.y;
                    __half2 x23 = __floats2half2_rn(acc[mt][nt][2] + bq2.x, acc[mt][nt][3] + bq2.y);
                    float2 f23 = __half22float2(htanh2(x23));
                    rowsum[mt][1] += f23.x * vv.x + f23.y * vv.y;
                }
            }
#pragma unroll
            for (int mt = 0; mt < 2; ++mt)
#pragma unroll
                for (int j = 0; j < 2; ++j) {
                    float v = rowsum[mt][j];
                    v += __shfl_xor_sync(0xffffffffu, v, 1);
                    v += __shfl_xor_sync(0xffffffffu, v, 2);
                    rowsum[mt][j] = v;
                }
            if (tig == 0) {
#pragma unroll
                for (int mt = 0; mt < 2; ++mt) {
                    int row = mwarp * 32 + mt * 16 + g;
                    srow[row * 4 + nwarp] = rowsum[mt][0];
                    srow[(row + 8) * 4 + nwarp] = rowsum[mt][1];
                }
            }
        }

        // ---- Prefetch next tile's values into regs freed by acc ----
        float4 pf[16];
        if (has_next) {
#pragma unroll
            for (int j = 0; j < 16; ++j) pf[j] = __ldg(v4n + tid + j * 512);
        }
        __syncthreads();   // srow visible

        // ---- exp / per-tile Z (rows 0..127) ----
        if (tid < TM) {
            float4 s4 = *(const float4*)(srow + tid * 4);
            float s = (s4.x + s4.y) + (s4.z + s4.w);
            float es = __expf(s);
            ses[tid] = es;
            g_escore[b * Tn + t0 + tid] = es;
            float zs = es;
#pragma unroll
            for (int o = 16; o; o >>= 1) zs += __shfl_xor_sync(0xffffffffu, zs, o);
            if (lane == 0) g_zp[tile * 4 + wid] = zs;
        }
        __syncthreads();   // ses visible

        // ---- Weighted column sum: partial[d] = sum_t es[t]*v_fp16[t][d] ----
        {
            float2 a2 = make_float2(0.f, 0.f);
#pragma unroll
            for (int j = 0; j < 32; ++j) {
                int t = grp * 32 + j;
                float es = ses[t];
                float2 v = __half22float2(*(const __half2*)&sA[t * SAW + c2]);
                a2.x += es * v.x;
                a2.y += es * v.y;
            }
            spart[grp * 128 + c2] = a2;
        }
        __syncthreads();   // spart visible; ALL A reads complete

        if (grp == 0) {
            float2 p0 = spart[c2], p1 = spart[128 + c2];
            float2 p2 = spart[256 + c2], p3 = spart[384 + c2];
            float2 r;
            r.x = (p0.x + p1.x) + (p2.x + p3.x);
            r.y = (p0.y + p1.y) + (p2.y + p3.y);
            *(float2*)(g_partial + (size_t)tile * Dn + 2 * c2) = r;
        }

        // ---- Stage next tile from pf regs into A ----
        if (has_next) {
            uint2* dst = (uint2*)sA;
#pragma unroll
            for (int j = 0; j < 16; ++j) {
                int i = tid + j * 512;
                dst[(i >> 6) * 66 + (i & 63)] =
                    make_uint2(pack_half2(pf[j].x, pf[j].y), pack_half2(pf[j].z, pf[j].w));
            }
        }
        __syncthreads();   // A staged; srow/ses/spart reusable
    }

    // ================= grid-wide sync, then in-kernel finalize =================
    __threadfence();
    __syncthreads();
    if (tid == 0) {
        atomicAdd(&g_tiles, 1);
        while (atomicAdd(&g_tiles, 0) < GRID_SCORE) __nanosleep(64);
    }
    __syncthreads();
    __threadfence();

    // CTAs 0..127: finalize slice (j = blk&7, b = blk>>3).
    if (blockIdx.x < 128) {
        const int j = blockIdx.x & 7, b = blockIdx.x >> 3;
        float* red = ses;                 // scratch
        float* cp = srow;                 // cpart[8][32]

        float invZ;
        {
            float s = (tid < 256) ? g_zp[b * 256 + tid] : 0.f;
#pragma unroll
            for (int o = 16; o; o >>= 1) s += __shfl_xor_sync(0xffffffffu, s, o);
            if (tid < 256 && lane == 0) red[wid] = s;
            __syncthreads();
            if (tid == 0) {
                float z = 0.f;
#pragma unroll
                for (int w = 0; w < 8; ++w) z += red[w];
                red[8] = 1.0f / z;
            }
            __syncthreads();
            invZ = red[8];
        }

        // Normalize weight slice: 1024 elems = 256 float4.
        if (tid < 256) {
            int i = j * 256 + tid;
            float4 v = ((const float4*)(g_escore + (size_t)b * Tn))[i];
            v.x *= invZ; v.y *= invZ; v.z *= invZ; v.w *= invZ;
            ((float4*)(w_out + (size_t)b * Tn))[i] = v;
        }

        // Context d-slice [j*32,+32): 8 tile-parts x 8 tiles, smem reduce.
        if (tid < 256) {
            const int ul = tid & 31, p = tid >> 5;
            const float* pp = g_partial + ((size_t)b * TPB + p * 8) * Dn + j * 32 + ul;
            float a = 0.f;
#pragma unroll
            for (int c = 0; c < 8; ++c) a += pp[(size_t)c * Dn];
            cp[p * 32 + ul] = a;
        }
        __syncthreads();
        if (tid < 32) {
            float t = 0.f;
#pragma unroll
            for (int p2 = 0; p2 < 8; ++p2) t += cp[p2 * 32 + tid];
            ctx_out[b * Dn + j * 32 + tid] = t * invZ;
        }
    }

    // Completion + deterministic flag reset (CTA 0 exits last).
    __syncthreads();
    if (tid == 0) {
        if (blockIdx.x == 0) {
            while (atomicAdd(&g_fin, 0) < GRID_SCORE - 1) __nanosleep(64);
            g_done = 0;
            g_tiles = 0;
            g_fin = 0;
            __threadfence();
        } else {
            __threadfence();
            atomicAdd(&g_fin, 1);
        }
    }
}

// ---------------- launch ----------------

extern "C" void kernel_launch(void* const* d_in, const int* in_sizes, int n_in,
                              void* d_out, int out_size) {
    const float* values = (const float*)d_in[0];
    const float* query  = (const float*)d_in[1];
    const float* W1w    = (const float*)d_in[2];
    const float* W1b    = (const float*)d_in[3];
    const float* W2w    = (const float*)d_in[4];
    const float* W2b    = (const float*)d_in[5];
    const float* Vw     = (const float*)d_in[6];
    // d_in[7] = V_b: softmax-invariant constant, intentionally unused.
    (void)in_sizes; (void)n_in; (void)out_size;

    float* ctx_out = (float*)d_out;             // [B, D]
    float* w_out   = (float*)d_out + Bn * Dn;   // [B, T, 1]

    cudaFuncSetAttribute(score_kernel, cudaFuncAttributeMaxDynamicSharedMemorySize, SM_TOTAL);

    score_kernel<<<GRID_SCORE, 512, SM_TOTAL>>>(values, W1w, Vw, query, W2w, W2b, W1b,
                                                ctx_out, w_out);
}

// round 17
// speedup vs baseline: 1.1591x; 1.1591x over previous
#include <cuda_runtime.h>
#include <cuda_fp16.h>
#include <cstdint>
#include <cstddef>

// BahdanauAttention B=16, T=8192, D=256, U=256 fp32.
// Baseline-PTX (ptxas sm_100): fp16 mma.sync + ldmatrix, SINGLE persistent kernel:
// biasq producer pre-phase, score GEMM (fragment double-buffered k-loop) +
// tanh(f16x2)*V epilogue + exp + per-tile context partials (values read ONCE),
// grid-wide spin sync, in-kernel finalize. 1 launch total.

#define Bn 16
#define Tn 8192
#define Dn 256
#define Un 256
#define TM 64                       // score tile M
#define TPB 128                     // tiles per batch
#define NTILES (Bn * TPB)           // 2048
#define GRID_SCORE 148
#define NPROD 128                   // producer CTAs (8 per batch)

__device__ float g_escore[Bn * Tn];        // exp(score)
__device__ float g_biasq[Bn * Un];
__device__ float g_zp[NTILES * 2];         // per-tile partial sums of exp
__device__ float g_partial[NTILES * Dn];   // per-tile unnormalized context partials
__device__ int   g_done;                   // biasq producer flag
__device__ int   g_tiles;                  // CTA tile-loop completion counter
__device__ int   g_fin;                    // finalize completion counter

// ---------------- helpers ----------------

__device__ __forceinline__ __half2 htanh2(__half2 x) {
    uint32_t xi = *(uint32_t*)&x, yo;
    asm("tanh.approx.f16x2 %0, %1;" : "=r"(yo) : "r"(xi));
    return *(__half2*)&yo;
}

__device__ __forceinline__ uint32_t pack_half2(float x, float y) {
    __half2 h = __floats2half2_rn(x, y);
    return *(uint32_t*)&h;
}

__device__ __forceinline__ uint32_t smem_u32(const void* p) {
    uint32_t a;
    asm("{ .reg .u64 t; cvta.to.shared.u64 t, %1; cvt.u32.u64 %0, t; }" : "=r"(a) : "l"(p));
    return a;
}

__device__ __forceinline__ void mma_fp16(float* c, const uint32_t* a, uint32_t b0, uint32_t b1) {
    asm volatile(
        "mma.sync.aligned.m16n8k16.row.col.f32.f16.f16.f32 "
        "{%0,%1,%2,%3},{%4,%5,%6,%7},{%8,%9},{%0,%1,%2,%3};"
        : "+f"(c[0]), "+f"(c[1]), "+f"(c[2]), "+f"(c[3])
        : "r"(a[0]), "r"(a[1]), "r"(a[2]), "r"(a[3]), "r"(b0), "r"(b1));
}

#define LDSM4(r, addr) \
    asm volatile("ldmatrix.sync.aligned.m8n8.x4.shared.b16 {%0,%1,%2,%3}, [%4];" \
                 : "=r"((r)[0]), "=r"((r)[1]), "=r"((r)[2]), "=r"((r)[3]) : "r"(addr))

// ---------------- smem layout (bytes) ----------------
#define SAW 132
#define ABUF_BYTES 33792                    // 64 rows x 132 words x 4B
#define SM_B (2 * ABUF_BYTES)               // 67584
#define SM_SROW (SM_B + 135168)             // 202752 : 64 x 8 floats = 2048
#define SM_SES (SM_SROW + 2048)             // 204800 : 64 floats
#define SM_SPART (SM_SES + 256)             // 205056 : 4 x 128 float2 = 4096
#define SM_TOTAL (SM_SPART + 4096)          // 209152

// ---------------- the single persistent kernel ----------------
// 512 threads (16 warps). Warp (mwarp=wid&1 -> 32 rows, nwarp=wid>>1 -> 32 cols).

__global__ __launch_bounds__(512, 1)
void score_kernel(const float* __restrict__ values, const float* __restrict__ W1,
                  const float* __restrict__ Vw, const float* __restrict__ query,
                  const float* __restrict__ W2, const float* __restrict__ W2b,
                  const float* __restrict__ W1b,
                  float* __restrict__ ctx_out, float* __restrict__ w_out) {
    extern __shared__ char smem[];
    uint32_t* sA = (uint32_t*)smem;
    uint32_t* sB = (uint32_t*)(smem + SM_B);
    float* srow = (float*)(smem + SM_SROW);
    float* ses = (float*)(smem + SM_SES);
    float2* spart = (float2*)(smem + SM_SPART);

    const int tid = threadIdx.x;
    const int wid = tid >> 5, lane = tid & 31;
    const int mwarp = wid & 1, nwarp = wid >> 1;
    const int g = lane >> 2, tig = lane & 3;

    // Stage B once: W1[k][u] -> sB[u][kp] (half2 of k-pair).
#pragma unroll 4
    for (int i = tid; i < 256 * 128; i += 512) {
        int u = i & 255, kp = i >> 8;
        float x0 = __ldg(W1 + (size_t)(2 * kp) * Un + u);
        float x1 = __ldg(W1 + (size_t)(2 * kp + 1) * Un + u);
        sB[u * SAW + kp] = pack_half2(x0, x1);
    }

    // Per-thread Vw pairs for cols c = nwarp*32 + nt*8 + 2tig + {0,1}.
    float2 vw2[4];
#pragma unroll
    for (int nt = 0; nt < 4; ++nt) {
        int c = nwarp * 32 + nt * 8 + 2 * tig;
        vw2[nt] = *(const float2*)(Vw + c);
    }

    const uint32_t sbA = smem_u32(sA), sbB = smem_u32(sB);
    const int t4 = lane >> 3, row_in = lane & 7;
    uint32_t adA[2];
#pragma unroll
    for (int mt = 0; mt < 2; ++mt) {
        int r = mwarp * 32 + mt * 16 + ((t4 & 1) << 3) + row_in;
        adA[mt] = sbA + (uint32_t)((r * SAW + ((t4 >> 1) << 2)) << 2);
    }
    uint32_t adB[2];
#pragma unroll
    for (int np = 0; np < 2; ++np) {
        int u = nwarp * 32 + np * 16 + ((t4 >> 1) << 3) + row_in;
        adB[np] = sbB + (uint32_t)((u * SAW + ((t4 & 1) << 2)) << 2);
    }

    // Prologue: stage first tile into buf0 (float4 loads, uint2 stores).
    {
        const int tile = blockIdx.x;
        const float4* v4 = (const float4*)(values + ((size_t)(tile >> 7) * Tn + (tile & 127) * TM) * Dn);
        uint2* dst = (uint2*)sA;
#pragma unroll
        for (int j = 0; j < 8; ++j) {
            int i = tid + j * 512;
            float4 x = __ldg(v4 + i);
            dst[(i >> 6) * 66 + (i & 63)] = make_uint2(pack_half2(x.x, x.y), pack_half2(x.z, x.w));
        }
    }
    __syncthreads();

    // Producer pre-phase: CTA k (k < 128) computes biasq[b, u0:u0+32).
    if (blockIdx.x < NPROD) {
        const int b = blockIdx.x >> 3;
        const int u0 = (blockIdx.x & 7) * 32;
        float* qsh = (float*)spart;               // 256 floats
        float* psh = srow;                        // 16 x 32 floats
        if (tid < Dn) qsh[tid] = __ldg(query + b * Dn + tid);
        __syncthreads();
        const int ul = tid & 31, dp = tid >> 5;   // 16 d-parts x 16 d each
        const float* W2c = W2 + (size_t)(dp * 16) * Un + u0 + ul;
        const float* qc = qsh + dp * 16;
        float a0 = 0.f, a1 = 0.f, a2 = 0.f, a3 = 0.f;
#pragma unroll
        for (int d = 0; d < 16; d += 4) {
            a0 += qc[d] * __ldg(W2c + (size_t)d * Un);
            a1 += qc[d + 1] * __ldg(W2c + (size_t)(d + 1) * Un);
            a2 += qc[d + 2] * __ldg(W2c + (size_t)(d + 2) * Un);
            a3 += qc[d + 3] * __ldg(W2c + (size_t)(d + 3) * Un);
        }
        psh[dp * 32 + ul] = (a0 + a1) + (a2 + a3);
        __syncthreads();
        if (tid < 32) {
            float s = 0.f;
#pragma unroll
            for (int p = 0; p < 16; ++p) s += psh[p * 32 + tid];
            int uu = u0 + tid;
            g_biasq[b * Un + uu] = s + __ldg(W2b + uu) + __ldg(W1b + uu);
        }
        __threadfence();
        __syncthreads();
        if (tid == 0) atomicAdd(&g_done, 1);
    }
    __syncthreads();   // spart/srow scratch free again

    const int c2 = tid & 127, grp = tid >> 7;
    const int ncta = (NTILES - blockIdx.x + GRID_SCORE - 1) / GRID_SCORE;

    // Fragment double buffers for the k-loop.
    uint32_t fa0[2][4], fa1[2][4], fb0[2][4], fb1[2][4];
#define LOADFRAG(buf, ks, abase) do {                    \
        uint32_t _ko = (uint32_t)(ks) * 32;              \
        LDSM4(fa0[buf], adA[0] + (abase) + _ko);         \
        LDSM4(fa1[buf], adA[1] + (abase) + _ko);         \
        LDSM4(fb0[buf], adB[0] + _ko);                   \
        LDSM4(fb1[buf], adB[1] + _ko);                   \
    } while (0)
#define MMA8(buf) do {                                   \
        mma_fp16(acc[0][0], fa0[buf], fb0[buf][0], fb0[buf][1]); \
        mma_fp16(acc[1][0], fa1[buf], fb0[buf][0], fb0[buf][1]); \
        mma_fp16(acc[0][1], fa0[buf], fb0[buf][2], fb0[buf][3]); \
        mma_fp16(acc[1][1], fa1[buf], fb0[buf][2], fb0[buf][3]); \
        mma_fp16(acc[0][2], fa0[buf], fb1[buf][0], fb1[buf][1]); \
        mma_fp16(acc[1][2], fa1[buf], fb1[buf][0], fb1[buf][1]); \
        mma_fp16(acc[0][3], fa0[buf], fb1[buf][2], fb1[buf][3]); \
        mma_fp16(acc[1][3], fa1[buf], fb1[buf][2], fb1[buf][3]); \
    } while (0)

    int bufi = 0;
    for (int it = 0; it < ncta; ++it) {
        const int tile = blockIdx.x + it * GRID_SCORE;
        const int b = tile >> 7;
        const int t0 = (tile & 127) * TM;
        const int ntile = tile + GRID_SCORE;
        const int has_next = ntile < NTILES;
        const float2* v2n = has_next
            ? (const float2*)(values + ((size_t)(ntile >> 7) * Tn + (ntile & 127) * TM) * Dn)
            : (const float2*)values;
        uint32_t* dst = (uint32_t*)(smem + (bufi ^ 1) * ABUF_BYTES);

        float acc[2][4][4];
#pragma unroll
        for (int mt = 0; mt < 2; ++mt)
#pragma unroll
            for (int nt = 0; nt < 4; ++nt)
#pragma unroll
                for (int q = 0; q < 4; ++q) acc[mt][nt][q] = 0.f;

        // First half prefetch (8 float2 = 16 regs).
        float2 pf[8];
        if (has_next) {
#pragma unroll
            for (int j = 0; j < 8; ++j) pf[j] = __ldg(v2n + tid + j * 512);
        }

        const uint32_t abase = (uint32_t)(bufi * ABUF_BYTES);

        // k-steps 0..7 with fragment double-buffering: LDSM(k+1) issued before MMA(k).
        LOADFRAG(0, 0, abase);
#pragma unroll
        for (int ks = 0; ks < 8; ++ks) {
            if (ks < 7) LOADFRAG((ks + 1) & 1, ks + 1, abase);
            MMA8(ks & 1);
        }

        // Store first half, prefetch second half (reuse pf regs).
        if (has_next) {
#pragma unroll
            for (int j = 0; j < 8; ++j) {
                int i = tid + j * 512;
                dst[(i >> 7) * SAW + (i & 127)] = pack_half2(pf[j].x, pf[j].y);
            }
#pragma unroll
            for (int j = 0; j < 8; ++j) pf[j] = __ldg(v2n + tid + (8 + j) * 512);
        }

        // k-steps 8..15.
        LOADFRAG(0, 8, abase);
#pragma unroll
        for (int ks = 8; ks < 16; ++ks) {
            if (ks < 15) LOADFRAG((ks + 1) & 1, ks + 1, abase);
            MMA8(ks & 1);
        }

        if (has_next) {
#pragma unroll
            for (int j = 0; j < 8; ++j) {
                int i = tid + (8 + j) * 512;
                dst[(i >> 7) * SAW + (i & 127)] = pack_half2(pf[j].x, pf[j].y);
            }
        }

        // Gate the FIRST epilogue on producer completion (biasq ready).
        if (it == 0) {
            if (tid == 0) {
                while (atomicAdd(&g_done, 0) < NPROD) __nanosleep(64);
            }
            __syncthreads();
            __threadfence();
        }

        // Epilogue: tanh(f16x2) of fp32-biased sums, fp32 product accumulation.
        const float* bq = g_biasq + b * Un;
        float rowsum[2][2] = {{0.f, 0.f}, {0.f, 0.f}};
#pragma unroll
        for (int nt = 0; nt < 4; ++nt) {
            int c = nwarp * 32 + nt * 8 + 2 * tig;
            float2 bq2 = __ldg((const float2*)(bq + c));
#pragma unroll
            for (int mt = 0; mt < 2; ++mt) {
                __half2 x01 = __floats2half2_rn(acc[mt][nt][0] + bq2.x, acc[mt][nt][1] + bq2.y);
                float2 f01 = __half22float2(htanh2(x01));
                rowsum[mt][0] += f01.x * vw2[nt].x + f01.y * vw2[nt].y;
                __half2 x23 = __floats2half2_rn(acc[mt][nt][2] + bq2.x, acc[mt][nt][3] + bq2.y);
                float2 f23 = __half22float2(htanh2(x23));
                rowsum[mt][1] += f23.x * vw2[nt].x + f23.y * vw2[nt].y;
            }
        }
#pragma unroll
        for (int mt = 0; mt < 2; ++mt)
#pragma unroll
            for (int j = 0; j < 2; ++j) {
                float v = rowsum[mt][j];
                v += __shfl_xor_sync(0xffffffffu, v, 1);
                v += __shfl_xor_sync(0xffffffffu, v, 2);
                rowsum[mt][j] = v;
            }
        if (tig == 0) {
#pragma unroll
            for (int mt = 0; mt < 2; ++mt) {
                int row = mwarp * 32 + mt * 16 + g;
                srow[row * 8 + nwarp] = rowsum[mt][0];
                srow[(row + 8) * 8 + nwarp] = rowsum[mt][1];
            }
        }
        __syncthreads();

        // Rows 0..63: final score, exp, per-tile Z partial.
        if (tid < TM) {
            const float4* s4 = (const float4*)(srow + tid * 8);
            float4 x = s4[0], y = s4[1];
            float s = ((x.x + x.y) + (x.z + x.w)) + ((y.x + y.y) + (y.z + y.w));
            float es = __expf(s);
            ses[tid] = es;
            g_escore[b * Tn + t0 + tid] = es;
            float zs = es;
#pragma unroll
            for (int o = 16; o; o >>= 1) zs += __shfl_xor_sync(0xffffffffu, zs, o);
            if (lane == 0) g_zp[tile * 2 + wid] = zs;
        }
        __syncthreads();

        // Weighted column sum from the fp16 tile: partial[d] = sum_t es[t]*v[t][d].
        {
            const uint32_t* sAv = (const uint32_t*)(smem + bufi * ABUF_BYTES);
            float2 a2 = make_float2(0.f, 0.f);
#pragma unroll
            for (int j = 0; j < 16; ++j) {
                int t = grp * 16 + j;
                float es = ses[t];
                float2 v = __half22float2(*(const __half2*)&sAv[t * SAW + c2]);
                a2.x += es * v.x;
                a2.y += es * v.y;
            }
            spart[grp * 128 + c2] = a2;
        }
        __syncthreads();
        if (grp == 0) {
            float2 p0 = spart[c2], p1 = spart[128 + c2];
            float2 p2 = spart[256 + c2], p3 = spart[384 + c2];
            float2 r;
            r.x = (p0.x + p1.x) + (p2.x + p3.x);
            r.y = (p0.y + p1.y) + (p2.y + p3.y);
            *(float2*)(g_partial + (size_t)tile * Dn + 2 * c2) = r;
        }
        // NOTE: no sync needed here (see prior-round analysis).
        bufi ^= 1;
    }

    // ================= grid-wide sync, then in-kernel finalize =================
    __threadfence();
    __syncthreads();
    if (tid == 0) {
        atomicAdd(&g_tiles, 1);
        while (atomicAdd(&g_tiles, 0) < GRID_SCORE) __nanosleep(64);
    }
    __syncthreads();
    __threadfence();

    // CTAs 0..127: finalize slice (j = blk&7, b = blk>>3).
    if (blockIdx.x < 128) {
        const int j = blockIdx.x & 7, b = blockIdx.x >> 3;
        float* red = ses;                 // scratch
        float* cp = srow;                 // cpart[8][32]

        float invZ;
        {
            float s = (tid < 256) ? g_zp[b * 256 + tid] : 0.f;
#pragma unroll
            for (int o = 16; o; o >>= 1) s += __shfl_xor_sync(0xffffffffu, s, o);
            if (tid < 256 && lane == 0) red[wid] = s;
            __syncthreads();
            if (tid == 0) {
                float z = 0.f;
#pragma unroll
                for (int w = 0; w < 8; ++w) z += red[w];
                red[8] = 1.0f / z;
            }
            __syncthreads();
            invZ = red[8];
        }

        // Normalize weight slice: 1024 elems = 256 float4.
        if (tid < 256) {
            int i = j * 256 + tid;
            float4 v = ((const float4*)(g_escore + (size_t)b * Tn))[i];
            v.x *= invZ; v.y *= invZ; v.z *= invZ; v.w *= invZ;
            ((float4*)(w_out + (size_t)b * Tn))[i] = v;
        }

        // Context d-slice [j*32,+32): 8 tile-parts x 16 tiles, smem reduce.
        if (tid < 256) {
            const int ul = tid & 31, p = tid >> 5;
            const float* pp = g_partial + ((size_t)b * TPB + p * 16) * Dn + j * 32 + ul;
            float a = 0.f;
#pragma unroll
            for (int c = 0; c < 16; ++c) a += pp[(size_t)c * Dn];
            cp[p * 32 + ul] = a;
        }
        __syncthreads();
        if (tid < 32) {
            float t = 0.f;
#pragma unroll
            for (int p2 = 0; p2 < 8; ++p2) t += cp[p2 * 32 + tid];
            ctx_out[b * Dn + j * 32 + tid] = t * invZ;
        }
    }

    // Completion + deterministic flag reset (CTA 0 exits last).
    __syncthreads();
    if (tid == 0) {
        if (blockIdx.x == 0) {
            while (atomicAdd(&g_fin, 0) < GRID_SCORE - 1) __nanosleep(64);
            g_done = 0;
            g_tiles = 0;
            g_fin = 0;
            __threadfence();
        } else {
            __threadfence();
            atomicAdd(&g_fin, 1);
        }
    }
}

// ---------------- launch ----------------

extern "C" void kernel_launch(void* const* d_in, const int* in_sizes, int n_in,
                              void* d_out, int out_size) {
    const float* values = (const float*)d_in[0];
    const float* query  = (const float*)d_in[1];
    const float* W1w    = (const float*)d_in[2];
    const float* W1b    = (const float*)d_in[3];
    const float* W2w    = (const float*)d_in[4];
    const float* W2b    = (const float*)d_in[5];
    const float* Vw     = (const float*)d_in[6];
    // d_in[7] = V_b: softmax-invariant constant, intentionally unused.
    (void)in_sizes; (void)n_in; (void)out_size;

    float* ctx_out = (float*)d_out;             // [B, D]
    float* w_out   = (float*)d_out + Bn * Dn;   // [B, T, 1]

    cudaFuncSetAttribute(score_kernel, cudaFuncAttributeMaxDynamicSharedMemorySize, SM_TOTAL);

    score_kernel<<<GRID_SCORE, 512, SM_TOTAL>>>(values, W1w, Vw, query, W2w, W2b, W1b,
                                                ctx_out, w_out);
}